// round 14
// baseline (speedup 1.0000x reference)
#include <cuda_runtime.h>
#include <cuda_fp16.h>
#include <cstdint>
#include <math.h>

// ---------------------------------------------------------------- dims
#define B_  16
#define C_  16
#define P_  512
#define D_  256
#define Z_  (B_*C_)            // 256 batches
#define BCPD (B_*C_*P_*D_)     // 33,554,432
#define BPD  (B_*P_*D_)        // 2,097,152
#define BCPP (B_*C_*P_*P_)     // 67,108,864
#define WELEM (C_*D_*D_)       // 1,048,576
#define NROWS ((long)Z_*P_)    // 131,072 attention rows

// ---------------------------------------------------------------- scratch
__device__ half g_qry[BCPD];
__device__ half g_ctx[BCPD];
__device__ half g_q[BCPD];
__device__ half g_k[BCPD];
__device__ half g_vT[BCPD];          // [z][e][kv]
__device__ half g_partial[BCPP];     // exp(s - blockmax) fp16
__device__ float2 g_stats[NROWS * 16];   // per (row, 32-col block): (max, sumexp)
__device__ half g_wqT[WELEM], g_wkT[WELEM], g_wvT[WELEM];

// ---------------------------------------------------------------- helpers
__device__ __forceinline__ uint32_t smem_u32(const void* p) {
    uint32_t a;
    asm("{ .reg .u64 t; cvta.to.shared.u64 t, %1; cvt.u32.u64 %0, t; }" : "=r"(a) : "l"(p));
    return a;
}

#define CP16(saddr, gaddr) \
    asm volatile("cp.async.cg.shared.global [%0], [%1], 16;" :: "r"(saddr), "l"(gaddr) : "memory")
#define CP_COMMIT() asm volatile("cp.async.commit_group;" ::: "memory")
#define CP_WAIT1()  asm volatile("cp.async.wait_group 1;" ::: "memory")
#define CP_WAIT0()  asm volatile("cp.async.wait_group 0;" ::: "memory")

#define LDSM4(r0, r1, r2, r3, addr) \
    asm volatile("ldmatrix.sync.aligned.m8n8.x4.shared.b16 {%0,%1,%2,%3}, [%4];" \
        : "=r"(r0), "=r"(r1), "=r"(r2), "=r"(r3) : "r"(addr))

#define MMAH(c, a, b) \
    asm volatile("mma.sync.aligned.m16n8k16.row.col.f32.f16.f16.f32 " \
        "{%0,%1,%2,%3}, {%4,%5,%6,%7}, {%8,%9}, {%0,%1,%2,%3};" \
        : "+f"((c)[0]), "+f"((c)[1]), "+f"((c)[2]), "+f"((c)[3]) \
        : "r"((a)[0]), "r"((a)[1]), "r"((a)[2]), "r"((a)[3]), "r"((b)[0]), "r"((b)[1]))

// ---------------------------------------------------------------- GEMM smem
// 3-stage cp.async pipeline: stage = 16KB A + 16KB B.
#define OFF_A    0
#define OFF_B    16384
#define STAGE_SZ 32768
#define NSTAGE   3
#define SMEM_SZ  (NSTAGE * STAGE_SZ)          // 98304
#define STG_LD   130        // fp32 stage pitch (floats)
#define STGH_LD  136        // fp16 stage pitch (halves)
// out GEMM (mode 2): factor table after the three stages
#define OFF_FT   SMEM_SZ
#define FT_PITCH 17         // half2 words per row (16 blocks + pad)
#define SMEM_SZ2 (OFF_FT + 128 * FT_PITCH * 4)   // 107008

// ================================================================ proj GEMM
// One launch for q/k/v projections. blockIdx.z = idx*256 + zz; idx 0=q,1=k,2=v.
__global__ __launch_bounds__(256, 2)
void proj_gemm(const half* __restrict__ Aq, const half* __restrict__ Actx,
               const half* __restrict__ Wq, const half* __restrict__ Wk,
               const half* __restrict__ Wv,
               const float* __restrict__ bq, const float* __restrict__ bk,
               const float* __restrict__ bv,
               half* __restrict__ Oq, half* __restrict__ Ok,
               half* __restrict__ Ov)
{
    extern __shared__ char smem[];
    const uint32_t sb = smem_u32(smem);

    const int t    = threadIdx.x;
    const int wid  = t >> 5;
    const int lane = t & 31;
    const int wr   = wid >> 2;
    const int wc   = wid & 3;

    const int zfull = blockIdx.z;
    const int idx = zfull >> 8;          // 0=q, 1=k, 2=v
    const int zz  = zfull & 255;
    const int bz  = zz & 15;             // cycle index
    const int m0 = blockIdx.y * 128;
    const int n0 = blockIdx.x * 128;

    const int M = P_, N = D_, K = D_;
    const long Kb = (long)K * 2;
    const half* Abase = (idx == 0) ? Aq : Actx;
    const half* Wbase = (idx == 0) ? Wq : (idx == 1) ? Wk : Wv;
    const float* bias = (idx == 0) ? bq : (idx == 1) ? bk : bv;
    const float scale = (idx == 0) ? 0.0625f : 1.0f;

    const char* gA = (const char*)(Abase + ((long)zz * M + m0) * K);
    const char* gB = (const char*)(Wbase + ((long)bz * N + n0) * K);

    uint32_t soffv[4]; long goffv[4];
#pragma unroll
    for (int i = 0; i < 4; i++) {
        int id = t + i * 256;
        int r = id >> 3, c = id & 7;
        soffv[i] = r * 128 + ((uint32_t)(c ^ (r & 7)) << 4);
        goffv[i] = (long)r * Kb + c * 16;
    }

    uint32_t roA[4]; int swA[4];
#pragma unroll
    for (int mi = 0; mi < 4; mi++) {
        int row = wr * 64 + mi * 16 + (lane & 15);
        roA[mi] = row * 128;
        swA[mi] = row & 7;
    }
    const int a_kc = lane >> 4;
    uint32_t roB[2]; int swB[2];
#pragma unroll
    for (int nj = 0; nj < 2; nj++) {
        int row = wc * 32 + nj * 16 + (lane & 7) + ((lane >> 4) << 3);
        roB[nj] = row * 128;
        swB[nj] = row & 7;
    }
    const int b_kc = (lane >> 3) & 1;

    float acc[4][4][4];
#pragma unroll
    for (int mi = 0; mi < 4; mi++)
#pragma unroll
        for (int ni = 0; ni < 4; ni++)
#pragma unroll
            for (int r = 0; r < 4; r++) acc[mi][ni][r] = 0.f;

    auto load_chunk = [&](int ch, int buf) {
        const uint32_t s = sb + buf * STAGE_SZ;
        const long gk = (long)ch * 128;
#pragma unroll
        for (int i = 0; i < 4; i++) {
            CP16(s + OFF_A + soffv[i], gA + goffv[i] + gk);
            CP16(s + OFF_B + soffv[i], gB + goffv[i] + gk);
        }
        CP_COMMIT();
    };

    const int nch = K >> 6;        // 4
    load_chunk(0, 0);
    load_chunk(1, 1);

    for (int ch = 0; ch < nch; ch++) {
        if (ch + 1 < nch) CP_WAIT1(); else CP_WAIT0();
        __syncthreads();
        if (ch + 2 < nch) load_chunk(ch + 2, (ch + 2) % NSTAGE);

        const uint32_t sA = sb + (ch % NSTAGE) * STAGE_SZ + OFF_A;
        const uint32_t sB = sb + (ch % NSTAGE) * STAGE_SZ + OFF_B;

#pragma unroll
        for (int ks = 0; ks < 4; ks++) {
            const int kcA = ks * 2 + a_kc;
            const int kcB = ks * 2 + b_kc;

            uint32_t a[4][4], b[4][2];
#pragma unroll
            for (int mi = 0; mi < 4; mi++)
                LDSM4(a[mi][0], a[mi][1], a[mi][2], a[mi][3],
                      sA + roA[mi] + ((uint32_t)(kcA ^ swA[mi]) << 4));
#pragma unroll
            for (int nj = 0; nj < 2; nj++)
                LDSM4(b[nj*2][0], b[nj*2][1], b[nj*2+1][0], b[nj*2+1][1],
                      sB + roB[nj] + ((uint32_t)(kcB ^ swB[nj]) << 4));
#pragma unroll
            for (int mi = 0; mi < 4; mi++)
#pragma unroll
                for (int ni = 0; ni < 4; ni++)
                    MMAH(acc[mi][ni], a[mi], b[ni]);
        }
    }
    __syncthreads();

    // epilogue via padded fp32 smem stage
    float* stg = reinterpret_cast<float*>(smem);
    {
        const int grp = lane >> 2;
        const int tq  = lane & 3;
#pragma unroll
        for (int mi = 0; mi < 4; mi++) {
            const int m = wr * 64 + mi * 16 + grp;
#pragma unroll
            for (int ni = 0; ni < 4; ni++) {
                const int n = wc * 32 + ni * 8 + 2 * tq;
                stg[m * STG_LD + n]           = acc[mi][ni][0];
                stg[m * STG_LD + n + 1]       = acc[mi][ni][1];
                stg[(m + 8) * STG_LD + n]     = acc[mi][ni][2];
                stg[(m + 8) * STG_LD + n + 1] = acc[mi][ni][3];
            }
        }
    }
    __syncthreads();

    const float* brow = bias + (long)bz * N + n0;

    if (idx < 2) {
        half* OutH = (idx == 0) ? Oq : Ok;
#pragma unroll
        for (int r = 0; r < 32; r++) {
            int id = r * 256 + t;
            int m = id >> 6, j = id & 63;
            int n = 2 * j;
            float v0 = fmaxf(stg[m * STG_LD + n]     + brow[n],     0.f) * scale;
            float v1 = fmaxf(stg[m * STG_LD + n + 1] + brow[n + 1], 0.f) * scale;
            long base = ((long)zz * M + m0 + m) * N + n0 + n;
            __half2 H; H.x = __float2half(v0); H.y = __float2half(v1);
            *reinterpret_cast<__half2*>(&OutH[base]) = H;
        }
    } else {
        // vT: Ov[zz][e][q]
#pragma unroll
        for (int r = 0; r < 32; r++) {
            int id = r * 256 + t;
            int e = id >> 6, j = id & 63;
            int q = 2 * j;
            float bv2 = brow[e];
            float v0 = fmaxf(stg[q * STG_LD + e]       + bv2, 0.f);
            float v1 = fmaxf(stg[(q + 1) * STG_LD + e] + bv2, 0.f);
            long base = ((long)zz * N + n0 + e) * M + m0 + q;
            __half2 H; H.x = __float2half(v0); H.y = __float2half(v1);
            *reinterpret_cast<__half2*>(&Ov[base]) = H;
        }
    }
}

// ================================================================ NT GEMM
// Out = A[z] @ B[z]^T.
// MODE 1: scores epilogue — block softmax partials + stats.
// MODE 2: out GEMM — A = fp16 exp-partials, scaled in-register by the
//         per-(row, 32-kv-block) softmax factor from Stats; fp32 out.
template<int MODE>
__global__ __launch_bounds__(256, 2)
void nt_gemm(const half* __restrict__ A, const half* __restrict__ B,
             float* __restrict__ OutF, half* __restrict__ OutH,
             float2* __restrict__ Stats, int M, int N, int K)
{
    extern __shared__ char smem[];
    const uint32_t sb = smem_u32(smem);

    const int t    = threadIdx.x;
    const int wid  = t >> 5;
    const int lane = t & 31;
    const int wr   = wid >> 2;
    const int wc   = wid & 3;
    const int grp  = lane >> 2;
    const int tq   = lane & 3;

    const int z  = blockIdx.z;
    const int m0 = blockIdx.y * 128;
    const int n0 = blockIdx.x * 128;

    const long Kb = (long)K * 2;
    const char* gA = (const char*)(A + ((long)z * M + m0) * K);
    const char* gB = (const char*)(B + ((long)z * N + n0) * K);

    // MODE 2: build per-row softmax factor table (128 rows x 16 blocks, half2)
    __half2* ft = reinterpret_cast<__half2*>(smem + OFF_FT);
    if (MODE == 2) {
        if (t < 128) {
            const float2* st = &Stats[((long)z * M + m0 + t) * 16];
            float bm[16], bs[16];
            float gm = -1e30f;
#pragma unroll
            for (int i = 0; i < 16; i++) {
                float2 s2 = st[i];
                bm[i] = s2.x; bs[i] = s2.y;
                gm = fmaxf(gm, s2.x);
            }
            float denom = 0.f;
            float ex[16];
#pragma unroll
            for (int i = 0; i < 16; i++) {
                ex[i] = __expf(bm[i] - gm);
                denom += bs[i] * ex[i];
            }
            float inv = 1.f / denom;
#pragma unroll
            for (int i = 0; i < 16; i++)
                ft[t * FT_PITCH + i] = __float2half2_rn(ex[i] * inv);
        }
        __syncthreads();
    }

    uint32_t soffv[4]; long goffv[4];
#pragma unroll
    for (int i = 0; i < 4; i++) {
        int id = t + i * 256;
        int r = id >> 3, c = id & 7;
        soffv[i] = r * 128 + ((uint32_t)(c ^ (r & 7)) << 4);
        goffv[i] = (long)r * Kb + c * 16;
    }

    uint32_t roA[4]; int swA[4];
#pragma unroll
    for (int mi = 0; mi < 4; mi++) {
        int row = wr * 64 + mi * 16 + (lane & 15);
        roA[mi] = row * 128;
        swA[mi] = row & 7;
    }
    const int a_kc = lane >> 4;
    uint32_t roB[2]; int swB[2];
#pragma unroll
    for (int nj = 0; nj < 2; nj++) {
        int row = wc * 32 + nj * 16 + (lane & 7) + ((lane >> 4) << 3);
        roB[nj] = row * 128;
        swB[nj] = row & 7;
    }
    const int b_kc = (lane >> 3) & 1;

    float acc[4][4][4];
#pragma unroll
    for (int mi = 0; mi < 4; mi++)
#pragma unroll
        for (int ni = 0; ni < 4; ni++)
#pragma unroll
            for (int r = 0; r < 4; r++) acc[mi][ni][r] = 0.f;

    auto load_chunk = [&](int ch, int buf) {
        const uint32_t s = sb + buf * STAGE_SZ;
        const long gk = (long)ch * 128;
#pragma unroll
        for (int i = 0; i < 4; i++) {
            CP16(s + OFF_A + soffv[i], gA + goffv[i] + gk);
            CP16(s + OFF_B + soffv[i], gB + goffv[i] + gk);
        }
        CP_COMMIT();
    };

    const int nch = K >> 6;
    load_chunk(0, 0);
    load_chunk(1, 1);

    for (int ch = 0; ch < nch; ch++) {
        if (ch + 1 < nch) CP_WAIT1(); else CP_WAIT0();
        __syncthreads();
        if (ch + 2 < nch) load_chunk(ch + 2, (ch + 2) % NSTAGE);

        const uint32_t sA = sb + (ch % NSTAGE) * STAGE_SZ + OFF_A;
        const uint32_t sB = sb + (ch % NSTAGE) * STAGE_SZ + OFF_B;

#pragma unroll
        for (int ks = 0; ks < 4; ks++) {
            const int kcA = ks * 2 + a_kc;
            const int kcB = ks * 2 + b_kc;

            uint32_t a[4][4], b[4][2];
#pragma unroll
            for (int mi = 0; mi < 4; mi++)
                LDSM4(a[mi][0], a[mi][1], a[mi][2], a[mi][3],
                      sA + roA[mi] + ((uint32_t)(kcA ^ swA[mi]) << 4));

            if (MODE == 2) {
                // scale A-fragments by per-(row, kv-block) softmax factor
                const int blk = ch * 2 + (ks >> 1);
#pragma unroll
                for (int mi = 0; mi < 4; mi++) {
                    const int r0 = wr * 64 + mi * 16 + grp;
                    __half2 f0 = ft[r0 * FT_PITCH + blk];
                    __half2 f1 = ft[(r0 + 8) * FT_PITCH + blk];
                    __half2* ah = reinterpret_cast<__half2*>(a[mi]);
                    ah[0] = __hmul2(ah[0], f0);
                    ah[1] = __hmul2(ah[1], f1);
                    ah[2] = __hmul2(ah[2], f0);
                    ah[3] = __hmul2(ah[3], f1);
                }
            }
#pragma unroll
            for (int nj = 0; nj < 2; nj++)
                LDSM4(b[nj*2][0], b[nj*2][1], b[nj*2+1][0], b[nj*2+1][1],
                      sB + roB[nj] + ((uint32_t)(kcB ^ swB[nj]) << 4));
#pragma unroll
            for (int mi = 0; mi < 4; mi++)
#pragma unroll
                for (int ni = 0; ni < 4; ni++)
                    MMAH(acc[mi][ni], a[mi], b[ni]);
        }
    }
    __syncthreads();

    if (MODE == 2) {
        float* stg = reinterpret_cast<float*>(smem);
#pragma unroll
        for (int mi = 0; mi < 4; mi++) {
            const int m = wr * 64 + mi * 16 + grp;
#pragma unroll
            for (int ni = 0; ni < 4; ni++) {
                const int n = wc * 32 + ni * 8 + 2 * tq;
                stg[m * STG_LD + n]           = acc[mi][ni][0];
                stg[m * STG_LD + n + 1]       = acc[mi][ni][1];
                stg[(m + 8) * STG_LD + n]     = acc[mi][ni][2];
                stg[(m + 8) * STG_LD + n + 1] = acc[mi][ni][3];
            }
        }
        __syncthreads();
#pragma unroll
        for (int r = 0; r < 64; r++) {
            int id = r * 256 + t;
            int m = id >> 7, n = id & 127;
            OutF[((long)z * M + m0 + m) * N + n0 + n] = stg[m * STG_LD + n];
        }
    } else {
        // ---- MODE 1: block softmax partials
        half* stgh = reinterpret_cast<half*>(smem);
        const int sblk = (n0 >> 5) + wc;   // 32-col block index 0..15
#pragma unroll
        for (int mi = 0; mi < 4; mi++) {
            const int r0 = wr * 64 + mi * 16 + grp;
            const int r1 = r0 + 8;
            float mx0 = -1e30f, mx1 = -1e30f;
#pragma unroll
            for (int ni = 0; ni < 4; ni++) {
                mx0 = fmaxf(mx0, fmaxf(acc[mi][ni][0], acc[mi][ni][1]));
                mx1 = fmaxf(mx1, fmaxf(acc[mi][ni][2], acc[mi][ni][3]));
            }
            mx0 = fmaxf(mx0, __shfl_xor_sync(0xffffffffu, mx0, 1));
            mx0 = fmaxf(mx0, __shfl_xor_sync(0xffffffffu, mx0, 2));
            mx1 = fmaxf(mx1, __shfl_xor_sync(0xffffffffu, mx1, 1));
            mx1 = fmaxf(mx1, __shfl_xor_sync(0xffffffffu, mx1, 2));

            float s0 = 0.f, s1 = 0.f;
#pragma unroll
            for (int ni = 0; ni < 4; ni++) {
                const int n = wc * 32 + ni * 8 + 2 * tq;
                float e00 = __expf(acc[mi][ni][0] - mx0);
                float e01 = __expf(acc[mi][ni][1] - mx0);
                float e10 = __expf(acc[mi][ni][2] - mx1);
                float e11 = __expf(acc[mi][ni][3] - mx1);
                s0 += e00 + e01;
                s1 += e10 + e11;
                __half2 h0 = __floats2half2_rn(e00, e01);
                __half2 h1 = __floats2half2_rn(e10, e11);
                *reinterpret_cast<__half2*>(&stgh[r0 * STGH_LD + n]) = h0;
                *reinterpret_cast<__half2*>(&stgh[r1 * STGH_LD + n]) = h1;
            }
            s0 += __shfl_xor_sync(0xffffffffu, s0, 1);
            s0 += __shfl_xor_sync(0xffffffffu, s0, 2);
            s1 += __shfl_xor_sync(0xffffffffu, s1, 1);
            s1 += __shfl_xor_sync(0xffffffffu, s1, 2);
            if (tq == 0) {
                Stats[((long)z * M + m0 + r0) * 16 + sblk] = make_float2(mx0, s0);
                Stats[((long)z * M + m0 + r1) * 16 + sblk] = make_float2(mx1, s1);
            }
        }
        __syncthreads();
        // coalesced fp16 partial write: 128 rows x 64 half2
#pragma unroll
        for (int r = 0; r < 32; r++) {
            int id = r * 256 + t;
            int m = id >> 6, c2 = id & 63;
            __half2 h = *reinterpret_cast<__half2*>(&stgh[m * STGH_LD + 2 * c2]);
            *reinterpret_cast<__half2*>(
                &OutH[((long)z * M + m0 + m) * N + n0 + 2 * c2]) = h;
        }
    }
}

// ================================================================ elementwise
__global__ __launch_bounds__(256) void ctx_qry_kernel(
        const float* __restrict__ q, const float* __restrict__ aw,
        half* __restrict__ qry16, half* __restrict__ ctx16)
{
    int idx = blockIdx.x * 256 + threadIdx.x;      // over BPD/2
    if (idx >= BPD / 2) return;
    int dp = idx & 127;
    int p  = (idx >> 7) & 511;
    int b  = idx >> 16;

    float2 qv[C_], pr[C_];
    float2 accv = make_float2(0.f, 0.f);
#pragma unroll
    for (int c = 0; c < C_; c++) {
        long qo = ((long)((b * C_ + c) * P_ + p)) * D_ + 2 * dp;
        long ao = ((long)(c * P_ + p)) * D_ + 2 * dp;
        float2 qq = *reinterpret_cast<const float2*>(&q[qo]);
        float2 w  = *reinterpret_cast<const float2*>(&aw[ao]);
        qv[c] = qq;
        pr[c].x = w.x * qq.x; pr[c].y = w.y * qq.y;
        accv.x += pr[c].x;    accv.y += pr[c].y;
    }
#pragma unroll
    for (int c = 0; c < C_; c++) {
        long o = ((long)((b * C_ + c) * P_ + p)) * D_ + 2 * dp;
        __half2 Cv; Cv.x = __float2half(accv.x - pr[c].x);
        Cv.y = __float2half(accv.y - pr[c].y);
        *reinterpret_cast<__half2*>(&ctx16[o]) = Cv;
        __half2 Qv; Qv.x = __float2half(qv[c].x);
        Qv.y = __float2half(qv[c].y);
        *reinterpret_cast<__half2*>(&qry16[o]) = Qv;
    }
}

// All three weight transposes in one launch: blockIdx.x in [0, 3072).
__global__ __launch_bounds__(256) void split_wT3_kernel(
        const float* __restrict__ wq, const float* __restrict__ wk,
        const float* __restrict__ wv,
        half* __restrict__ wqT, half* __restrict__ wkT, half* __restrict__ wvT)
{
    __shared__ float s[32][33];
    const int sel = blockIdx.x >> 10;        // 0=q,1=k,2=v
    const int blk = blockIdx.x & 1023;
    const float* w = (sel == 0) ? wq : (sel == 1) ? wk : wv;
    half* wT       = (sel == 0) ? wqT : (sel == 1) ? wkT : wvT;

    int bc = blk >> 6;
    int t6 = blk & 63;
    int e0 = (t6 >> 3) * 32, d0 = (t6 & 7) * 32;
    int tx = threadIdx.x & 31, ty = threadIdx.x >> 5;
#pragma unroll
    for (int r = 0; r < 4; r++) {
        int row = ty + r * 8;
        s[row][tx] = w[((long)bc * 256 + d0 + row) * 256 + e0 + tx];
    }
    __syncthreads();
#pragma unroll
    for (int r = 0; r < 4; r++) {
        int row = ty + r * 8;
        wT[((long)bc * 256 + e0 + row) * 256 + d0 + tx] = __float2half(s[tx][row]);
    }
}

// ================================================================ launcher
extern "C" void kernel_launch(void* const* d_in, const int* in_sizes, int n_in,
                              void* d_out, int out_size)
{
    const float* query = (const float*)d_in[0];
    const float* aw    = (const float*)d_in[1];
    const float* qw    = (const float*)d_in[2];
    const float* kw    = (const float*)d_in[3];
    const float* vw    = (const float*)d_in[4];
    const float* qb    = (const float*)d_in[5];
    const float* kb    = (const float*)d_in[6];
    const float* vb    = (const float*)d_in[7];
    float* out = (float*)d_out;

    half *qry16, *ctx16, *qB, *kB, *vT, *partial;
    half *wqT, *wkT, *wvT;
    float2* stats;
    cudaGetSymbolAddress((void**)&qry16, g_qry);
    cudaGetSymbolAddress((void**)&ctx16, g_ctx);
    cudaGetSymbolAddress((void**)&qB, g_q);
    cudaGetSymbolAddress((void**)&kB, g_k);
    cudaGetSymbolAddress((void**)&vT, g_vT);
    cudaGetSymbolAddress((void**)&partial, g_partial);
    cudaGetSymbolAddress((void**)&stats, g_stats);
    cudaGetSymbolAddress((void**)&wqT, g_wqT);
    cudaGetSymbolAddress((void**)&wkT, g_wkT);
    cudaGetSymbolAddress((void**)&wvT, g_wvT);

    cudaFuncSetAttribute(proj_gemm,  cudaFuncAttributeMaxDynamicSharedMemorySize, SMEM_SZ);
    cudaFuncSetAttribute(nt_gemm<1>, cudaFuncAttributeMaxDynamicSharedMemorySize, SMEM_SZ);
    cudaFuncSetAttribute(nt_gemm<2>, cudaFuncAttributeMaxDynamicSharedMemorySize, SMEM_SZ2);

    // 1) fused context + query fp16 conversion; merged weight transposes
    ctx_qry_kernel<<<BPD / 2 / 256, 256>>>(query, aw, qry16, ctx16);
    split_wT3_kernel<<<3072, 256>>>(qw, kw, vw, wqT, wkT, wvT);

    // 2) all three projections in one launch
    {
        dim3 g(D_ / 128, P_ / 128, 3 * Z_);
        proj_gemm<<<g, 256, SMEM_SZ>>>(qry16, ctx16, wqT, wkT, wvT,
                                       qb, kb, vb, qB, kB, vT);
    }
    // 3) scores GEMM + block-softmax partials (fp16 partials + stats)
    {
        dim3 g(P_ / 128, P_ / 128, Z_);
        nt_gemm<1><<<g, 256, SMEM_SZ>>>(qB, kB, nullptr, partial, stats,
                                        P_, P_, D_);
    }
    // 4) out = softmax-scaled partials @ vT^T -> fp32 (combine folded in)
    {
        dim3 g(D_ / 128, P_ / 128, Z_);
        nt_gemm<2><<<g, 256, SMEM_SZ2>>>(partial, vT, out, nullptr, stats,
                                         P_, D_, P_);
    }
}

// round 16
// speedup vs baseline: 1.0234x; 1.0234x over previous
#include <cuda_runtime.h>
#include <cuda_fp16.h>
#include <cstdint>
#include <math.h>

// ---------------------------------------------------------------- dims
#define B_  16
#define C_  16
#define P_  512
#define D_  256
#define Z_  (B_*C_)            // 256 batches
#define BCPD (B_*C_*P_*D_)     // 33,554,432
#define BPD  (B_*P_*D_)        // 2,097,152
#define BCPP (B_*C_*P_*P_)     // 67,108,864
#define WELEM (C_*D_*D_)       // 1,048,576
#define NROWS ((long)Z_*P_)    // 131,072 attention rows

// ---------------------------------------------------------------- scratch
__device__ half g_qry[BCPD];
__device__ half g_ctx[BCPD];
__device__ half g_q[BCPD];
__device__ half g_k[BCPD];
__device__ half g_vT[BCPD];          // [z][e][kv]
__device__ half g_partial[BCPP];     // exp(s - blockmax) fp16
__device__ float2 g_stats[NROWS * 16];   // per (row, 32-col block): (max, sumexp)
__device__ half g_wqT[WELEM], g_wkT[WELEM], g_wvT[WELEM];

// ---------------------------------------------------------------- helpers
__device__ __forceinline__ uint32_t smem_u32(const void* p) {
    uint32_t a;
    asm("{ .reg .u64 t; cvta.to.shared.u64 t, %1; cvt.u32.u64 %0, t; }" : "=r"(a) : "l"(p));
    return a;
}

#define CP16(saddr, gaddr) \
    asm volatile("cp.async.cg.shared.global [%0], [%1], 16;" :: "r"(saddr), "l"(gaddr) : "memory")
#define CP_COMMIT() asm volatile("cp.async.commit_group;" ::: "memory")
#define CP_WAIT1()  asm volatile("cp.async.wait_group 1;" ::: "memory")
#define CP_WAIT0()  asm volatile("cp.async.wait_group 0;" ::: "memory")

#define LDSM4(r0, r1, r2, r3, addr) \
    asm volatile("ldmatrix.sync.aligned.m8n8.x4.shared.b16 {%0,%1,%2,%3}, [%4];" \
        : "=r"(r0), "=r"(r1), "=r"(r2), "=r"(r3) : "r"(addr))

#define MMAH(c, a, b) \
    asm volatile("mma.sync.aligned.m16n8k16.row.col.f32.f16.f16.f32 " \
        "{%0,%1,%2,%3}, {%4,%5,%6,%7}, {%8,%9}, {%0,%1,%2,%3};" \
        : "+f"((c)[0]), "+f"((c)[1]), "+f"((c)[2]), "+f"((c)[3]) \
        : "r"((a)[0]), "r"((a)[1]), "r"((a)[2]), "r"((a)[3]), "r"((b)[0]), "r"((b)[1]))

// ---------------------------------------------------------------- GEMM smem
#define OFF_A    0
#define OFF_B    16384
#define STAGE_SZ 32768
#define SMEM_SZ  66560                 // 2-stage + fp32 epilogue stage
#define SMEM_SZ3 (3 * STAGE_SZ)        // 98304 (3-stage, scores only)
#define STG_LD   130        // fp32 stage pitch (floats)
#define STGH_LD  136        // fp16 stage pitch (halves)
// out GEMM (mode 2, 2-stage): factor table after the two stages
#define OFF_FT   65536
#define FT_PITCH 17         // half2 words per row (16 blocks + pad)
#define SMEM_SZ2 (OFF_FT + 128 * FT_PITCH * 4)   // 74240

// ================================================================ proj GEMM
// One launch for q/k/v projections. blockIdx.z = idx*256 + zz; idx 0=q,1=k,2=v.
__global__ __launch_bounds__(256, 2)
void proj_gemm(const half* __restrict__ Aq, const half* __restrict__ Actx,
               const half* __restrict__ Wq, const half* __restrict__ Wk,
               const half* __restrict__ Wv,
               const float* __restrict__ bq, const float* __restrict__ bk,
               const float* __restrict__ bv,
               half* __restrict__ Oq, half* __restrict__ Ok,
               half* __restrict__ Ov)
{
    extern __shared__ char smem[];
    const uint32_t sb = smem_u32(smem);

    const int t    = threadIdx.x;
    const int wid  = t >> 5;
    const int lane = t & 31;
    const int wr   = wid >> 2;
    const int wc   = wid & 3;

    const int zfull = blockIdx.z;
    const int idx = zfull >> 8;          // 0=q, 1=k, 2=v
    const int zz  = zfull & 255;
    const int bz  = zz & 15;             // cycle index
    const int m0 = blockIdx.y * 128;
    const int n0 = blockIdx.x * 128;

    const int M = P_, N = D_, K = D_;
    const long Kb = (long)K * 2;
    const half* Abase = (idx == 0) ? Aq : Actx;
    const half* Wbase = (idx == 0) ? Wq : (idx == 1) ? Wk : Wv;
    const float* bias = (idx == 0) ? bq : (idx == 1) ? bk : bv;
    const float scale = (idx == 0) ? 0.0625f : 1.0f;

    const char* gA = (const char*)(Abase + ((long)zz * M + m0) * K);
    const char* gB = (const char*)(Wbase + ((long)bz * N + n0) * K);

    uint32_t soffv[4]; long goffv[4];
#pragma unroll
    for (int i = 0; i < 4; i++) {
        int id = t + i * 256;
        int r = id >> 3, c = id & 7;
        soffv[i] = r * 128 + ((uint32_t)(c ^ (r & 7)) << 4);
        goffv[i] = (long)r * Kb + c * 16;
    }

    uint32_t roA[4]; int swA[4];
#pragma unroll
    for (int mi = 0; mi < 4; mi++) {
        int row = wr * 64 + mi * 16 + (lane & 15);
        roA[mi] = row * 128;
        swA[mi] = row & 7;
    }
    const int a_kc = lane >> 4;
    uint32_t roB[2]; int swB[2];
#pragma unroll
    for (int nj = 0; nj < 2; nj++) {
        int row = wc * 32 + nj * 16 + (lane & 7) + ((lane >> 4) << 3);
        roB[nj] = row * 128;
        swB[nj] = row & 7;
    }
    const int b_kc = (lane >> 3) & 1;

    float acc[4][4][4];
#pragma unroll
    for (int mi = 0; mi < 4; mi++)
#pragma unroll
        for (int ni = 0; ni < 4; ni++)
#pragma unroll
            for (int r = 0; r < 4; r++) acc[mi][ni][r] = 0.f;

    auto load_chunk = [&](int ch, int buf) {
        const uint32_t s = sb + buf * STAGE_SZ;
        const long gk = (long)ch * 128;
#pragma unroll
        for (int i = 0; i < 4; i++) {
            CP16(s + OFF_A + soffv[i], gA + goffv[i] + gk);
            CP16(s + OFF_B + soffv[i], gB + goffv[i] + gk);
        }
        CP_COMMIT();
    };

    load_chunk(0, 0);

    const int nch = K >> 6;
    for (int ch = 0; ch < nch; ch++) {
        const int buf = ch & 1;
        if (ch + 1 < nch) { load_chunk(ch + 1, (ch + 1) & 1); CP_WAIT1(); }
        else              { CP_WAIT0(); }
        __syncthreads();

        const uint32_t sA = sb + buf * STAGE_SZ + OFF_A;
        const uint32_t sB = sb + buf * STAGE_SZ + OFF_B;

#pragma unroll
        for (int ks = 0; ks < 4; ks++) {
            const int kcA = ks * 2 + a_kc;
            const int kcB = ks * 2 + b_kc;

            uint32_t a[4][4], b[4][2];
#pragma unroll
            for (int mi = 0; mi < 4; mi++)
                LDSM4(a[mi][0], a[mi][1], a[mi][2], a[mi][3],
                      sA + roA[mi] + ((uint32_t)(kcA ^ swA[mi]) << 4));
#pragma unroll
            for (int nj = 0; nj < 2; nj++)
                LDSM4(b[nj*2][0], b[nj*2][1], b[nj*2+1][0], b[nj*2+1][1],
                      sB + roB[nj] + ((uint32_t)(kcB ^ swB[nj]) << 4));
#pragma unroll
            for (int mi = 0; mi < 4; mi++)
#pragma unroll
                for (int ni = 0; ni < 4; ni++)
                    MMAH(acc[mi][ni], a[mi], b[ni]);
        }
        __syncthreads();
    }

    // epilogue via padded fp32 smem stage
    float* stg = reinterpret_cast<float*>(smem);
    {
        const int grp = lane >> 2;
        const int tq  = lane & 3;
#pragma unroll
        for (int mi = 0; mi < 4; mi++) {
            const int m = wr * 64 + mi * 16 + grp;
#pragma unroll
            for (int ni = 0; ni < 4; ni++) {
                const int n = wc * 32 + ni * 8 + 2 * tq;
                stg[m * STG_LD + n]           = acc[mi][ni][0];
                stg[m * STG_LD + n + 1]       = acc[mi][ni][1];
                stg[(m + 8) * STG_LD + n]     = acc[mi][ni][2];
                stg[(m + 8) * STG_LD + n + 1] = acc[mi][ni][3];
            }
        }
    }
    __syncthreads();

    const float* brow = bias + (long)bz * N + n0;

    if (idx < 2) {
        half* OutH = (idx == 0) ? Oq : Ok;
#pragma unroll
        for (int r = 0; r < 32; r++) {
            int id = r * 256 + t;
            int m = id >> 6, j = id & 63;
            int n = 2 * j;
            float v0 = fmaxf(stg[m * STG_LD + n]     + brow[n],     0.f) * scale;
            float v1 = fmaxf(stg[m * STG_LD + n + 1] + brow[n + 1], 0.f) * scale;
            long base = ((long)zz * M + m0 + m) * N + n0 + n;
            __half2 H; H.x = __float2half(v0); H.y = __float2half(v1);
            *reinterpret_cast<__half2*>(&OutH[base]) = H;
        }
    } else {
        // vT: Ov[zz][e][q]
#pragma unroll
        for (int r = 0; r < 32; r++) {
            int id = r * 256 + t;
            int e = id >> 6, j = id & 63;
            int q = 2 * j;
            float bv2 = brow[e];
            float v0 = fmaxf(stg[q * STG_LD + e]       + bv2, 0.f);
            float v1 = fmaxf(stg[(q + 1) * STG_LD + e] + bv2, 0.f);
            long base = ((long)zz * N + n0 + e) * M + m0 + q;
            __half2 H; H.x = __float2half(v0); H.y = __float2half(v1);
            *reinterpret_cast<__half2*>(&Ov[base]) = H;
        }
    }
}

// ================================================================ NT GEMM
// Out = A[z] @ B[z]^T.
// MODE 1: scores epilogue — block softmax partials + stats.
// MODE 2: out GEMM — A = fp16 exp-partials, scaled in-register by the
//         per-(row, 32-kv-block) softmax factor from Stats; fp32 out.
// NST: cp.async pipeline depth (2 or 3).
template<int MODE, int NST>
__global__ __launch_bounds__(256, 2)
void nt_gemm(const half* __restrict__ A, const half* __restrict__ B,
             float* __restrict__ OutF, half* __restrict__ OutH,
             float2* __restrict__ Stats, int M, int N, int K)
{
    extern __shared__ char smem[];
    const uint32_t sb = smem_u32(smem);

    const int t    = threadIdx.x;
    const int wid  = t >> 5;
    const int lane = t & 31;
    const int wr   = wid >> 2;
    const int wc   = wid & 3;
    const int grp  = lane >> 2;
    const int tq   = lane & 3;

    const int z  = blockIdx.z;
    const int m0 = blockIdx.y * 128;
    const int n0 = blockIdx.x * 128;

    const long Kb = (long)K * 2;
    const char* gA = (const char*)(A + ((long)z * M + m0) * K);
    const char* gB = (const char*)(B + ((long)z * N + n0) * K);

    // MODE 2: build per-row softmax factor table (128 rows x 16 blocks, half2)
    __half2* ft = reinterpret_cast<__half2*>(smem + OFF_FT);
    if (MODE == 2) {
        if (t < 128) {
            const float2* st = &Stats[((long)z * M + m0 + t) * 16];
            float bm[16], bs[16];
            float gm = -1e30f;
#pragma unroll
            for (int i = 0; i < 16; i++) {
                float2 s2 = st[i];
                bm[i] = s2.x; bs[i] = s2.y;
                gm = fmaxf(gm, s2.x);
            }
            float denom = 0.f;
            float ex[16];
#pragma unroll
            for (int i = 0; i < 16; i++) {
                ex[i] = __expf(bm[i] - gm);
                denom += bs[i] * ex[i];
            }
            float inv = 1.f / denom;
#pragma unroll
            for (int i = 0; i < 16; i++)
                ft[t * FT_PITCH + i] = __float2half2_rn(ex[i] * inv);
        }
        __syncthreads();
    }

    uint32_t soffv[4]; long goffv[4];
#pragma unroll
    for (int i = 0; i < 4; i++) {
        int id = t + i * 256;
        int r = id >> 3, c = id & 7;
        soffv[i] = r * 128 + ((uint32_t)(c ^ (r & 7)) << 4);
        goffv[i] = (long)r * Kb + c * 16;
    }

    uint32_t roA[4]; int swA[4];
#pragma unroll
    for (int mi = 0; mi < 4; mi++) {
        int row = wr * 64 + mi * 16 + (lane & 15);
        roA[mi] = row * 128;
        swA[mi] = row & 7;
    }
    const int a_kc = lane >> 4;
    uint32_t roB[2]; int swB[2];
#pragma unroll
    for (int nj = 0; nj < 2; nj++) {
        int row = wc * 32 + nj * 16 + (lane & 7) + ((lane >> 4) << 3);
        roB[nj] = row * 128;
        swB[nj] = row & 7;
    }
    const int b_kc = (lane >> 3) & 1;

    float acc[4][4][4];
#pragma unroll
    for (int mi = 0; mi < 4; mi++)
#pragma unroll
        for (int ni = 0; ni < 4; ni++)
#pragma unroll
            for (int r = 0; r < 4; r++) acc[mi][ni][r] = 0.f;

    auto load_chunk = [&](int ch, int buf) {
        const uint32_t s = sb + buf * STAGE_SZ;
        const long gk = (long)ch * 128;
#pragma unroll
        for (int i = 0; i < 4; i++) {
            CP16(s + OFF_A + soffv[i], gA + goffv[i] + gk);
            CP16(s + OFF_B + soffv[i], gB + goffv[i] + gk);
        }
        CP_COMMIT();
    };

    const int nch = K >> 6;

    auto mainloop_body = [&](int ch, uint32_t sA, uint32_t sB) {
#pragma unroll
        for (int ks = 0; ks < 4; ks++) {
            const int kcA = ks * 2 + a_kc;
            const int kcB = ks * 2 + b_kc;

            uint32_t a[4][4], b[4][2];
#pragma unroll
            for (int mi = 0; mi < 4; mi++)
                LDSM4(a[mi][0], a[mi][1], a[mi][2], a[mi][3],
                      sA + roA[mi] + ((uint32_t)(kcA ^ swA[mi]) << 4));

            if (MODE == 2) {
                // scale A-fragments by per-(row, kv-block) softmax factor
                const int blk = ch * 2 + (ks >> 1);
#pragma unroll
                for (int mi = 0; mi < 4; mi++) {
                    const int r0 = wr * 64 + mi * 16 + grp;
                    __half2 f0 = ft[r0 * FT_PITCH + blk];
                    __half2 f1 = ft[(r0 + 8) * FT_PITCH + blk];
                    __half2* ah = reinterpret_cast<__half2*>(a[mi]);
                    ah[0] = __hmul2(ah[0], f0);
                    ah[1] = __hmul2(ah[1], f1);
                    ah[2] = __hmul2(ah[2], f0);
                    ah[3] = __hmul2(ah[3], f1);
                }
            }
#pragma unroll
            for (int nj = 0; nj < 2; nj++)
                LDSM4(b[nj*2][0], b[nj*2][1], b[nj*2+1][0], b[nj*2+1][1],
                      sB + roB[nj] + ((uint32_t)(kcB ^ swB[nj]) << 4));
#pragma unroll
            for (int mi = 0; mi < 4; mi++)
#pragma unroll
                for (int ni = 0; ni < 4; ni++)
                    MMAH(acc[mi][ni], a[mi], b[ni]);
        }
    };

    if (NST == 2) {
        load_chunk(0, 0);
        for (int ch = 0; ch < nch; ch++) {
            const int buf = ch & 1;
            if (ch + 1 < nch) { load_chunk(ch + 1, (ch + 1) & 1); CP_WAIT1(); }
            else              { CP_WAIT0(); }
            __syncthreads();
            mainloop_body(ch, sb + buf * STAGE_SZ + OFF_A,
                              sb + buf * STAGE_SZ + OFF_B);
            __syncthreads();
        }
    } else {
        load_chunk(0, 0);
        load_chunk(1, 1);
        for (int ch = 0; ch < nch; ch++) {
            if (ch + 1 < nch) CP_WAIT1(); else CP_WAIT0();
            __syncthreads();
            if (ch + 2 < nch) load_chunk(ch + 2, (ch + 2) % 3);
            mainloop_body(ch, sb + (ch % 3) * STAGE_SZ + OFF_A,
                              sb + (ch % 3) * STAGE_SZ + OFF_B);
        }
        __syncthreads();
    }

    if (MODE == 2) {
        float* stg = reinterpret_cast<float*>(smem);
#pragma unroll
        for (int mi = 0; mi < 4; mi++) {
            const int m = wr * 64 + mi * 16 + grp;
#pragma unroll
            for (int ni = 0; ni < 4; ni++) {
                const int n = wc * 32 + ni * 8 + 2 * tq;
                stg[m * STG_LD + n]           = acc[mi][ni][0];
                stg[m * STG_LD + n + 1]       = acc[mi][ni][1];
                stg[(m + 8) * STG_LD + n]     = acc[mi][ni][2];
                stg[(m + 8) * STG_LD + n + 1] = acc[mi][ni][3];
            }
        }
        __syncthreads();
#pragma unroll
        for (int r = 0; r < 64; r++) {
            int id = r * 256 + t;
            int m = id >> 7, n = id & 127;
            OutF[((long)z * M + m0 + m) * N + n0 + n] = stg[m * STG_LD + n];
        }
    } else {
        // ---- MODE 1: block softmax partials
        half* stgh = reinterpret_cast<half*>(smem);
        const int sblk = (n0 >> 5) + wc;   // 32-col block index 0..15
#pragma unroll
        for (int mi = 0; mi < 4; mi++) {
            const int r0 = wr * 64 + mi * 16 + grp;
            const int r1 = r0 + 8;
            float mx0 = -1e30f, mx1 = -1e30f;
#pragma unroll
            for (int ni = 0; ni < 4; ni++) {
                mx0 = fmaxf(mx0, fmaxf(acc[mi][ni][0], acc[mi][ni][1]));
                mx1 = fmaxf(mx1, fmaxf(acc[mi][ni][2], acc[mi][ni][3]));
            }
            mx0 = fmaxf(mx0, __shfl_xor_sync(0xffffffffu, mx0, 1));
            mx0 = fmaxf(mx0, __shfl_xor_sync(0xffffffffu, mx0, 2));
            mx1 = fmaxf(mx1, __shfl_xor_sync(0xffffffffu, mx1, 1));
            mx1 = fmaxf(mx1, __shfl_xor_sync(0xffffffffu, mx1, 2));

            float s0 = 0.f, s1 = 0.f;
#pragma unroll
            for (int ni = 0; ni < 4; ni++) {
                const int n = wc * 32 + ni * 8 + 2 * tq;
                float e00 = __expf(acc[mi][ni][0] - mx0);
                float e01 = __expf(acc[mi][ni][1] - mx0);
                float e10 = __expf(acc[mi][ni][2] - mx1);
                float e11 = __expf(acc[mi][ni][3] - mx1);
                s0 += e00 + e01;
                s1 += e10 + e11;
                __half2 h0 = __floats2half2_rn(e00, e01);
                __half2 h1 = __floats2half2_rn(e10, e11);
                *reinterpret_cast<__half2*>(&stgh[r0 * STGH_LD + n]) = h0;
                *reinterpret_cast<__half2*>(&stgh[r1 * STGH_LD + n]) = h1;
            }
            s0 += __shfl_xor_sync(0xffffffffu, s0, 1);
            s0 += __shfl_xor_sync(0xffffffffu, s0, 2);
            s1 += __shfl_xor_sync(0xffffffffu, s1, 1);
            s1 += __shfl_xor_sync(0xffffffffu, s1, 2);
            if (tq == 0) {
                Stats[((long)z * M + m0 + r0) * 16 + sblk] = make_float2(mx0, s0);
                Stats[((long)z * M + m0 + r1) * 16 + sblk] = make_float2(mx1, s1);
            }
        }
        __syncthreads();
        // coalesced fp16 partial write: 128 rows x 64 half2
#pragma unroll
        for (int r = 0; r < 32; r++) {
            int id = r * 256 + t;
            int m = id >> 6, c2 = id & 63;
            __half2 h = *reinterpret_cast<__half2*>(&stgh[m * STGH_LD + 2 * c2]);
            *reinterpret_cast<__half2*>(
                &OutH[((long)z * M + m0 + m) * N + n0 + 2 * c2]) = h;
        }
    }
}

// ================================================================ elementwise
__global__ __launch_bounds__(256) void ctx_qry_kernel(
        const float* __restrict__ q, const float* __restrict__ aw,
        half* __restrict__ qry16, half* __restrict__ ctx16)
{
    int idx = blockIdx.x * 256 + threadIdx.x;      // over BPD/2
    if (idx >= BPD / 2) return;
    int dp = idx & 127;
    int p  = (idx >> 7) & 511;
    int b  = idx >> 16;

    float2 qv[C_], pr[C_];
    float2 accv = make_float2(0.f, 0.f);
#pragma unroll
    for (int c = 0; c < C_; c++) {
        long qo = ((long)((b * C_ + c) * P_ + p)) * D_ + 2 * dp;
        long ao = ((long)(c * P_ + p)) * D_ + 2 * dp;
        float2 qq = *reinterpret_cast<const float2*>(&q[qo]);
        float2 w  = *reinterpret_cast<const float2*>(&aw[ao]);
        qv[c] = qq;
        pr[c].x = w.x * qq.x; pr[c].y = w.y * qq.y;
        accv.x += pr[c].x;    accv.y += pr[c].y;
    }
#pragma unroll
    for (int c = 0; c < C_; c++) {
        long o = ((long)((b * C_ + c) * P_ + p)) * D_ + 2 * dp;
        __half2 Cv; Cv.x = __float2half(accv.x - pr[c].x);
        Cv.y = __float2half(accv.y - pr[c].y);
        *reinterpret_cast<__half2*>(&ctx16[o]) = Cv;
        __half2 Qv; Qv.x = __float2half(qv[c].x);
        Qv.y = __float2half(qv[c].y);
        *reinterpret_cast<__half2*>(&qry16[o]) = Qv;
    }
}

// All three weight transposes in one launch: blockIdx.x in [0, 3072).
__global__ __launch_bounds__(256) void split_wT3_kernel(
        const float* __restrict__ wq, const float* __restrict__ wk,
        const float* __restrict__ wv,
        half* __restrict__ wqT, half* __restrict__ wkT, half* __restrict__ wvT)
{
    __shared__ float s[32][33];
    const int sel = blockIdx.x >> 10;        // 0=q,1=k,2=v
    const int blk = blockIdx.x & 1023;
    const float* w = (sel == 0) ? wq : (sel == 1) ? wk : wv;
    half* wT       = (sel == 0) ? wqT : (sel == 1) ? wkT : wvT;

    int bc = blk >> 6;
    int t6 = blk & 63;
    int e0 = (t6 >> 3) * 32, d0 = (t6 & 7) * 32;
    int tx = threadIdx.x & 31, ty = threadIdx.x >> 5;
#pragma unroll
    for (int r = 0; r < 4; r++) {
        int row = ty + r * 8;
        s[row][tx] = w[((long)bc * 256 + d0 + row) * 256 + e0 + tx];
    }
    __syncthreads();
#pragma unroll
    for (int r = 0; r < 4; r++) {
        int row = ty + r * 8;
        wT[((long)bc * 256 + e0 + row) * 256 + d0 + tx] = __float2half(s[tx][row]);
    }
}

// ================================================================ launcher
extern "C" void kernel_launch(void* const* d_in, const int* in_sizes, int n_in,
                              void* d_out, int out_size)
{
    const float* query = (const float*)d_in[0];
    const float* aw    = (const float*)d_in[1];
    const float* qw    = (const float*)d_in[2];
    const float* kw    = (const float*)d_in[3];
    const float* vw    = (const float*)d_in[4];
    const float* qb    = (const float*)d_in[5];
    const float* kb    = (const float*)d_in[6];
    const float* vb    = (const float*)d_in[7];
    float* out = (float*)d_out;

    half *qry16, *ctx16, *qB, *kB, *vT, *partial;
    half *wqT, *wkT, *wvT;
    float2* stats;
    cudaGetSymbolAddress((void**)&qry16, g_qry);
    cudaGetSymbolAddress((void**)&ctx16, g_ctx);
    cudaGetSymbolAddress((void**)&qB, g_q);
    cudaGetSymbolAddress((void**)&kB, g_k);
    cudaGetSymbolAddress((void**)&vT, g_vT);
    cudaGetSymbolAddress((void**)&partial, g_partial);
    cudaGetSymbolAddress((void**)&stats, g_stats);
    cudaGetSymbolAddress((void**)&wqT, g_wqT);
    cudaGetSymbolAddress((void**)&wkT, g_wkT);
    cudaGetSymbolAddress((void**)&wvT, g_wvT);

    cudaFuncSetAttribute(proj_gemm,    cudaFuncAttributeMaxDynamicSharedMemorySize, SMEM_SZ);
    cudaFuncSetAttribute(nt_gemm<1,3>, cudaFuncAttributeMaxDynamicSharedMemorySize, SMEM_SZ3);
    cudaFuncSetAttribute(nt_gemm<2,2>, cudaFuncAttributeMaxDynamicSharedMemorySize, SMEM_SZ2);

    // 1) fused context + query fp16 conversion; merged weight transposes
    ctx_qry_kernel<<<BPD / 2 / 256, 256>>>(query, aw, qry16, ctx16);
    split_wT3_kernel<<<3072, 256>>>(qw, kw, vw, wqT, wkT, wvT);

    // 2) all three projections in one launch (2-stage, round-12 config)
    {
        dim3 g(D_ / 128, P_ / 128, 3 * Z_);
        proj_gemm<<<g, 256, SMEM_SZ>>>(qry16, ctx16, wqT, wkT, wvT,
                                       qb, kb, vb, qB, kB, vT);
    }
    // 3) scores GEMM + block-softmax partials (3-stage pipeline)
    {
        dim3 g(P_ / 128, P_ / 128, Z_);
        nt_gemm<1,3><<<g, 256, SMEM_SZ3>>>(qB, kB, nullptr, partial, stats,
                                           P_, P_, D_);
    }
    // 4) out = softmax-scaled partials @ vT^T -> fp32 (2-stage, round-12 config)
    {
        dim3 g(D_ / 128, P_ / 128, Z_);
        nt_gemm<2,2><<<g, 256, SMEM_SZ2>>>(partial, vT, out, nullptr, stats,
                                           P_, D_, P_);
    }
}